// round 1
// baseline (speedup 1.0000x reference)
#include <cuda_runtime.h>
#include <math.h>

#define NB   2
#define NM   9
#define NS   8      // support maps = M-1
#define ND   256
#define NH   48
#define NHW  2304   // 48*48
#define NCLS 4
#define OW   224

// -------- device scratch (no allocations allowed) --------
__device__ float        g_invq[NB * NHW];            // 1/|q| per (b, pix)
__device__ float        g_invs[NB * NS * NHW];       // 1/|s| per (b, m, pix)
__device__ unsigned char g_cmask[NB * NS * NHW];     // 4-bit class mask per key
__device__ unsigned int g_logits[NB * NCLS * NHW];   // order-encoded float max

// order-preserving float<->uint encode for atomicMax
__device__ __forceinline__ unsigned enc_f(float f) {
    unsigned u = __float_as_uint(f);
    return (u & 0x80000000u) ? ~u : (u | 0x80000000u);
}
__device__ __forceinline__ float dec_f(unsigned e) {
    return (e & 0x80000000u) ? __uint_as_float(e & 0x7FFFFFFFu)
                             : __uint_as_float(~e);
}

// -------- 1) inverse norms along D for query + supports --------
__global__ void norm_kernel(const float* __restrict__ emb) {
    int idx = blockIdx.x * blockDim.x + threadIdx.x;
    if (idx >= NB * NM * NHW) return;
    int pix = idx % NHW;
    int t   = idx / NHW;
    int m   = t % NM;
    int b   = t / NM;
    const float* p = emb + ((size_t)(b * NM + m) * ND) * NHW + pix;
    float s = 0.f;
#pragma unroll 8
    for (int d = 0; d < ND; d++) {
        float v = p[(size_t)d * NHW];
        s += v * v;
    }
    float inv = 1.0f / fmaxf(sqrtf(s), 1e-12f);
    if (m == 0) g_invq[b * NHW + pix] = inv;
    else        g_invs[(b * NS + (m - 1)) * NHW + pix] = inv;
}

// -------- 2) class bitmask per key (background rewrite on channel 0) --------
__global__ void cmask_kernel(const float* __restrict__ pm) {
    int idx = blockIdx.x * blockDim.x + threadIdx.x;
    if (idx >= NB * NS * NHW) return;
    int pix = idx % NHW;
    int t   = idx / NHW;
    int m   = t % NS;
    int b   = t / NS;
    const float* base = pm + ((size_t)(b * NS + m) * NCLS) * NHW + pix;
    unsigned msk = 0;
    if (base[1 * NHW] != 0.f) msk |= 2u;
    if (base[2 * NHW] != 0.f) msk |= 4u;
    if (base[3 * NHW] != 0.f) msk |= 8u;
    if (msk == 0u) msk = 1u;   // background := no foreground class present
    g_cmask[idx] = (unsigned char)msk;
}

// -------- 3) init logits to encoded -inf --------
__global__ void init_logits_kernel() {
    int idx = blockIdx.x * blockDim.x + threadIdx.x;
    if (idx < NB * NCLS * NHW) g_logits[idx] = 0x007FFFFFu; // enc(-inf)
}

// -------- 4) fused normalized-GEMM + per-class masked max --------
// grid: (144 key tiles, 18 query tiles, 2 batches); 256 threads; 128x128 tile.
__global__ __launch_bounds__(256, 1)
void gemm_max_kernel(const float* __restrict__ emb) {
    const int b  = blockIdx.z;
    const int qt = blockIdx.y;           // 0..17
    const int kt = blockIdx.x;           // 0..143
    const int m  = kt / (NHW / 128);     // 2304/128 = 18 tiles per support map
    const int kpixbase = (kt % (NHW / 128)) * 128;
    const int qbase    = qt * 128;

    __shared__ float As[16][128];
    __shared__ float Bs[16][128];

    const int tid = threadIdx.x;
    const int tx  = tid & 15;
    const int ty  = tid >> 4;

    const float* qptr = emb + ((size_t)(b * NM + 0) * ND) * NHW;
    const float* sptr = emb + ((size_t)(b * NM + 1 + m) * ND) * NHW;
    const float* invq = g_invq + b * NHW + qbase;
    const float* invs = g_invs + (b * NS + m) * NHW + kpixbase;

    float acc[8][8];
#pragma unroll
    for (int i = 0; i < 8; i++)
#pragma unroll
        for (int j = 0; j < 8; j++) acc[i][j] = 0.f;

    for (int ks = 0; ks < ND; ks += 16) {
#pragma unroll
        for (int r = 0; r < 8; r++) {
            int e   = tid + r * 256;
            int dk  = e >> 7;
            int col = e & 127;
            As[dk][col] = qptr[(size_t)(ks + dk) * NHW + qbase + col] * invq[col];
            Bs[dk][col] = sptr[(size_t)(ks + dk) * NHW + kpixbase + col] * invs[col];
        }
        __syncthreads();
#pragma unroll
        for (int kk = 0; kk < 16; kk++) {
            float a[8], bb[8];
#pragma unroll
            for (int i = 0; i < 8; i++) a[i] = As[kk][i * 16 + ty];
#pragma unroll
            for (int j = 0; j < 8; j++) bb[j] = Bs[kk][j * 16 + tx];
#pragma unroll
            for (int i = 0; i < 8; i++)
#pragma unroll
                for (int j = 0; j < 8; j++) acc[i][j] = fmaf(a[i], bb[j], acc[i][j]);
        }
        __syncthreads();
    }

    // per-class masked max over this thread's 8 key columns
    float cmax[8][NCLS];
#pragma unroll
    for (int i = 0; i < 8; i++)
#pragma unroll
        for (int n = 0; n < NCLS; n++) cmax[i][n] = -INFINITY;

#pragma unroll
    for (int j = 0; j < 8; j++) {
        int kpix = kpixbase + j * 16 + tx;
        unsigned cm = g_cmask[(b * NS + m) * NHW + kpix];
#pragma unroll
        for (int n = 0; n < NCLS; n++) {
            if ((cm >> n) & 1u) {
#pragma unroll
                for (int i = 0; i < 8; i++)
                    cmax[i][n] = fmaxf(cmax[i][n], acc[i][j]);
            }
        }
    }

    // reduce across the 16 tx lanes (same queries, different keys) via shfl
#pragma unroll
    for (int off = 8; off > 0; off >>= 1) {
#pragma unroll
        for (int i = 0; i < 8; i++)
#pragma unroll
            for (int n = 0; n < NCLS; n++)
                cmax[i][n] = fmaxf(cmax[i][n],
                                   __shfl_xor_sync(0xffffffffu, cmax[i][n], off, 16));
    }

    if (tx == 0) {
#pragma unroll
        for (int i = 0; i < 8; i++) {
            int qg = qbase + i * 16 + ty;
#pragma unroll
            for (int n = 0; n < NCLS; n++)
                atomicMax(&g_logits[(b * NCLS + n) * NHW + qg], enc_f(cmax[i][n]));
        }
    }
}

// -------- 5) bilinear resize 48 -> 224 (jax.image.resize semantics) --------
__device__ __forceinline__ void taps(int o, int& ia, int& ib, float& wa, float& wb) {
    float x  = (o + 0.5f) * ((float)NH / (float)OW) - 0.5f;
    int   i0 = (int)floorf(x);
    float f  = x - (float)i0;
    if (i0 < 0)            { ia = 0;      ib = 0;      wa = 1.f;     wb = 0.f; }
    else if (i0 >= NH - 1) { ia = NH - 1; ib = NH - 1; wa = 1.f;     wb = 0.f; }
    else                   { ia = i0;     ib = i0 + 1; wa = 1.f - f; wb = f;   }
}

__global__ void resize_kernel(float* __restrict__ out) {
    int idx = blockIdx.x * blockDim.x + threadIdx.x;
    if (idx >= NB * NCLS * OW * OW) return;
    int ox = idx % OW;
    int oy = (idx / OW) % OW;
    int n  = (idx / (OW * OW)) % NCLS;
    int b  = idx / (NCLS * OW * OW);

    int ixa, ixb, iya, iyb;
    float wxa, wxb, wya, wyb;
    taps(ox, ixa, ixb, wxa, wxb);
    taps(oy, iya, iyb, wya, wyb);

    const unsigned* lg = g_logits + (b * NCLS + n) * NHW;
    float v = 0.f;
    if (wya > 0.f) {
        float row = 0.f;
        if (wxa > 0.f) row += wxa * dec_f(lg[iya * NH + ixa]);
        if (wxb > 0.f) row += wxb * dec_f(lg[iya * NH + ixb]);
        v += wya * row;
    }
    if (wyb > 0.f) {
        float row = 0.f;
        if (wxa > 0.f) row += wxa * dec_f(lg[iyb * NH + ixa]);
        if (wxb > 0.f) row += wxb * dec_f(lg[iyb * NH + ixb]);
        v += wyb * row;
    }
    if (n == 0 && isinf(v) && v < 0.f) v = 0.f;
    out[idx] = v;
}

// -------- launch --------
extern "C" void kernel_launch(void* const* d_in, const int* in_sizes, int n_in,
                              void* d_out, int out_size) {
    const float* emb = (const float*)d_in[0];   // (2,9,256,48,48)
    const float* pm  = (const float*)d_in[1];   // (2,8,4,48,48)
    float* out = (float*)d_out;                 // (2,4,224,224)

    {
        int total = NB * NM * NHW;
        norm_kernel<<<(total + 255) / 256, 256>>>(emb);
    }
    {
        int total = NB * NS * NHW;
        cmask_kernel<<<(total + 255) / 256, 256>>>(pm);
    }
    {
        int total = NB * NCLS * NHW;
        init_logits_kernel<<<(total + 255) / 256, 256>>>();
    }
    {
        dim3 grid(NS * (NHW / 128), NHW / 128, NB);   // (144, 18, 2)
        gemm_max_kernel<<<grid, 256>>>(emb);
    }
    {
        int total = NB * NCLS * OW * OW;
        resize_kernel<<<(total + 255) / 256, 256>>>(out);
    }
}

// round 2
// speedup vs baseline: 1.5025x; 1.5025x over previous
#include <cuda_runtime.h>
#include <math.h>

#define NB   2
#define NM   9
#define NS   8
#define ND   256
#define NH   48
#define NHW  2304
#define NCLS 4
#define OW   224

// -------- device scratch --------
__device__ float        g_qn[NB * ND * NHW];            // normalized query
__device__ float        g_sn[NB * NS * ND * NHW];       // normalized supports
__device__ unsigned char g_cmask[NB * NS * NHW];
__device__ unsigned int g_logits[NB * NCLS * NHW];

// order-preserving float<->uint encode for atomicMax
__device__ __forceinline__ unsigned enc_f(float f) {
    unsigned u = __float_as_uint(f);
    return (u & 0x80000000u) ? ~u : (u | 0x80000000u);
}
__device__ __forceinline__ float dec_f(unsigned e) {
    return (e & 0x80000000u) ? __uint_as_float(e & 0x7FFFFFFFu)
                             : __uint_as_float(~e);
}

// packed fp32x2 helpers (sm_103a)
__device__ __forceinline__ unsigned long long pack2(float x, float y) {
    unsigned long long r;
    asm("mov.b64 %0, {%1,%2};" : "=l"(r) : "f"(x), "f"(y));
    return r;
}
__device__ __forceinline__ void fma2(unsigned long long& c,
                                     unsigned long long a,
                                     unsigned long long b) {
    asm("fma.rn.f32x2 %0, %1, %2, %0;" : "+l"(c) : "l"(a), "l"(b));
}
__device__ __forceinline__ void unpack2(unsigned long long v, float& x, float& y) {
    asm("mov.b64 {%0,%1}, %2;" : "=f"(x), "=f"(y) : "l"(v));
}

union F4U2 { float4 f4; unsigned long long u2[2]; };

// -------- 1) normalize embeddings along D into scratch --------
__global__ void normalize_kernel(const float* __restrict__ emb) {
    int idx = blockIdx.x * blockDim.x + threadIdx.x;
    if (idx >= NB * NM * NHW) return;
    int pix = idx % NHW;
    int t   = idx / NHW;
    int m   = t % NM;
    int b   = t / NM;
    const float* p = emb + ((size_t)(b * NM + m) * ND) * NHW + pix;
    float s = 0.f;
#pragma unroll 8
    for (int d = 0; d < ND; d++) {
        float v = p[(size_t)d * NHW];
        s += v * v;
    }
    float inv = 1.0f / fmaxf(sqrtf(s), 1e-12f);
    float* dst = (m == 0) ? (g_qn + ((size_t)b * ND) * NHW + pix)
                          : (g_sn + ((size_t)((b * NS + (m - 1)) * ND)) * NHW + pix);
#pragma unroll 8
    for (int d = 0; d < ND; d++) {
        dst[(size_t)d * NHW] = p[(size_t)d * NHW] * inv;
    }
}

// -------- 2) class bitmask per key --------
__global__ void cmask_kernel(const float* __restrict__ pm) {
    int idx = blockIdx.x * blockDim.x + threadIdx.x;
    if (idx >= NB * NS * NHW) return;
    int pix = idx % NHW;
    int t   = idx / NHW;
    int m   = t % NS;
    int b   = t / NS;
    const float* base = pm + ((size_t)(b * NS + m) * NCLS) * NHW + pix;
    unsigned msk = 0;
    if (base[1 * NHW] != 0.f) msk |= 2u;
    if (base[2 * NHW] != 0.f) msk |= 4u;
    if (base[3 * NHW] != 0.f) msk |= 8u;
    if (msk == 0u) msk = 1u;
    g_cmask[idx] = (unsigned char)msk;
}

// -------- 3) init logits --------
__global__ void init_logits_kernel() {
    int idx = blockIdx.x * blockDim.x + threadIdx.x;
    if (idx < NB * NCLS * NHW) g_logits[idx] = 0x007FFFFFu; // enc(-inf)
}

// -------- 4) fused GEMM (packed f32x2) + per-class masked max --------
// 128x128 tile, 256 threads, 8x8 per thread, double-buffered smem.
__global__ __launch_bounds__(256, 1)
void gemm_max_kernel() {
    const int b  = blockIdx.z;
    const int qt = blockIdx.y;
    const int kt = blockIdx.x;
    const int m  = kt / (NHW / 128);
    const int kpixbase = (kt % (NHW / 128)) * 128;
    const int qbase    = qt * 128;

    __shared__ float As[2][16][128];
    __shared__ float Bs[2][16][128];

    const int tid = threadIdx.x;
    const int tx  = tid & 15;
    const int ty  = tid >> 4;
    const int tx4 = tx * 4;
    const int ty4 = ty * 4;

    // global-load mapping: thread covers float4 #tid and #(tid+256) of the
    // 512-float4 (16x128) stage tile.
    const int dk0 = tid >> 5;          // 0..7
    const int c0  = (tid & 31) * 4;    // 0..124
    const int dk1 = dk0 + 8;

    const float* qsrc = g_qn + ((size_t)b * ND) * NHW + qbase;
    const float* ssrc = g_sn + ((size_t)((b * NS + m) * ND)) * NHW + kpixbase;

    unsigned long long acc[8][4];
#pragma unroll
    for (int i = 0; i < 8; i++)
#pragma unroll
        for (int j = 0; j < 4; j++) acc[i][j] = 0ull;

    // prologue: load stage 0
    float4 ra0 = *(const float4*)(qsrc + (size_t)(0 + dk0) * NHW + c0);
    float4 ra1 = *(const float4*)(qsrc + (size_t)(0 + dk1) * NHW + c0);
    float4 rb0 = *(const float4*)(ssrc + (size_t)(0 + dk0) * NHW + c0);
    float4 rb1 = *(const float4*)(ssrc + (size_t)(0 + dk1) * NHW + c0);
    *(float4*)&As[0][dk0][c0] = ra0;
    *(float4*)&As[0][dk1][c0] = ra1;
    *(float4*)&Bs[0][dk0][c0] = rb0;
    *(float4*)&Bs[0][dk1][c0] = rb1;
    __syncthreads();

#pragma unroll 1
    for (int s = 0; s < 16; s++) {
        const int buf = s & 1;
        if (s < 15) {
            int d = (s + 1) * 16;
            ra0 = *(const float4*)(qsrc + (size_t)(d + dk0) * NHW + c0);
            ra1 = *(const float4*)(qsrc + (size_t)(d + dk1) * NHW + c0);
            rb0 = *(const float4*)(ssrc + (size_t)(d + dk0) * NHW + c0);
            rb1 = *(const float4*)(ssrc + (size_t)(d + dk1) * NHW + c0);
        }
#pragma unroll
        for (int kk = 0; kk < 16; kk++) {
            F4U2 a0, a1, b0, b1;
            a0.f4 = *(const float4*)&As[buf][kk][ty4];
            a1.f4 = *(const float4*)&As[buf][kk][64 + ty4];
            b0.f4 = *(const float4*)&Bs[buf][kk][tx4];
            b1.f4 = *(const float4*)&Bs[buf][kk][64 + tx4];
            unsigned long long ad[8];
            ad[0] = pack2(a0.f4.x, a0.f4.x);
            ad[1] = pack2(a0.f4.y, a0.f4.y);
            ad[2] = pack2(a0.f4.z, a0.f4.z);
            ad[3] = pack2(a0.f4.w, a0.f4.w);
            ad[4] = pack2(a1.f4.x, a1.f4.x);
            ad[5] = pack2(a1.f4.y, a1.f4.y);
            ad[6] = pack2(a1.f4.z, a1.f4.z);
            ad[7] = pack2(a1.f4.w, a1.f4.w);
#pragma unroll
            for (int i = 0; i < 8; i++) {
                fma2(acc[i][0], ad[i], b0.u2[0]);
                fma2(acc[i][1], ad[i], b0.u2[1]);
                fma2(acc[i][2], ad[i], b1.u2[0]);
                fma2(acc[i][3], ad[i], b1.u2[1]);
            }
        }
        if (s < 15) {
            __syncthreads();
            const int nbuf = buf ^ 1;
            *(float4*)&As[nbuf][dk0][c0] = ra0;
            *(float4*)&As[nbuf][dk1][c0] = ra1;
            *(float4*)&Bs[nbuf][dk0][c0] = rb0;
            *(float4*)&Bs[nbuf][dk1][c0] = rb1;
            __syncthreads();
        }
    }

    // ---- epilogue: per-class masked max ----
    // thread's k columns (8): {tx4+0..3, 64+tx4+0..3}
    unsigned cm[8];
    const unsigned char* cmb = g_cmask + (b * NS + m) * NHW + kpixbase;
#pragma unroll
    for (int j = 0; j < 4; j++) {
        cm[j]     = cmb[tx4 + j];
        cm[4 + j] = cmb[64 + tx4 + j];
    }

    float cmax[8][NCLS];
#pragma unroll
    for (int i = 0; i < 8; i++)
#pragma unroll
        for (int n = 0; n < NCLS; n++) cmax[i][n] = -INFINITY;

#pragma unroll
    for (int i = 0; i < 8; i++) {
        float v[8];
        unpack2(acc[i][0], v[0], v[1]);
        unpack2(acc[i][1], v[2], v[3]);
        unpack2(acc[i][2], v[4], v[5]);
        unpack2(acc[i][3], v[6], v[7]);
#pragma unroll
        for (int j = 0; j < 8; j++) {
            unsigned msk = cm[j];
#pragma unroll
            for (int n = 0; n < NCLS; n++)
                if ((msk >> n) & 1u) cmax[i][n] = fmaxf(cmax[i][n], v[j]);
        }
    }

    // reduce across the 16 tx lanes (width-16 shfl within half-warp)
#pragma unroll
    for (int off = 8; off > 0; off >>= 1) {
#pragma unroll
        for (int i = 0; i < 8; i++)
#pragma unroll
            for (int n = 0; n < NCLS; n++)
                cmax[i][n] = fmaxf(cmax[i][n],
                                   __shfl_xor_sync(0xffffffffu, cmax[i][n], off, 16));
    }

    if (tx == 0) {
#pragma unroll
        for (int i = 0; i < 8; i++) {
            int qg = qbase + ((i < 4) ? (ty4 + i) : (64 + ty4 + (i - 4)));
#pragma unroll
            for (int n = 0; n < NCLS; n++)
                atomicMax(&g_logits[(b * NCLS + n) * NHW + qg], enc_f(cmax[i][n]));
        }
    }
}

// -------- 5) bilinear resize 48 -> 224 --------
__device__ __forceinline__ void taps(int o, int& ia, int& ib, float& wa, float& wb) {
    float x  = (o + 0.5f) * ((float)NH / (float)OW) - 0.5f;
    int   i0 = (int)floorf(x);
    float f  = x - (float)i0;
    if (i0 < 0)            { ia = 0;      ib = 0;      wa = 1.f;     wb = 0.f; }
    else if (i0 >= NH - 1) { ia = NH - 1; ib = NH - 1; wa = 1.f;     wb = 0.f; }
    else                   { ia = i0;     ib = i0 + 1; wa = 1.f - f; wb = f;   }
}

__global__ void resize_kernel(float* __restrict__ out) {
    int idx = blockIdx.x * blockDim.x + threadIdx.x;
    if (idx >= NB * NCLS * OW * OW) return;
    int ox = idx % OW;
    int oy = (idx / OW) % OW;
    int n  = (idx / (OW * OW)) % NCLS;
    int b  = idx / (NCLS * OW * OW);

    int ixa, ixb, iya, iyb;
    float wxa, wxb, wya, wyb;
    taps(ox, ixa, ixb, wxa, wxb);
    taps(oy, iya, iyb, wya, wyb);

    const unsigned* lg = g_logits + (b * NCLS + n) * NHW;
    float v = 0.f;
    if (wya > 0.f) {
        float row = 0.f;
        if (wxa > 0.f) row += wxa * dec_f(lg[iya * NH + ixa]);
        if (wxb > 0.f) row += wxb * dec_f(lg[iya * NH + ixb]);
        v += wya * row;
    }
    if (wyb > 0.f) {
        float row = 0.f;
        if (wxa > 0.f) row += wxa * dec_f(lg[iyb * NH + ixa]);
        if (wxb > 0.f) row += wxb * dec_f(lg[iyb * NH + ixb]);
        v += wyb * row;
    }
    if (n == 0 && isinf(v) && v < 0.f) v = 0.f;
    out[idx] = v;
}

// -------- launch --------
extern "C" void kernel_launch(void* const* d_in, const int* in_sizes, int n_in,
                              void* d_out, int out_size) {
    const float* emb = (const float*)d_in[0];
    const float* pm  = (const float*)d_in[1];
    float* out = (float*)d_out;

    {
        int total = NB * NM * NHW;
        normalize_kernel<<<(total + 255) / 256, 256>>>(emb);
    }
    {
        int total = NB * NS * NHW;
        cmask_kernel<<<(total + 255) / 256, 256>>>(pm);
    }
    {
        int total = NB * NCLS * NHW;
        init_logits_kernel<<<(total + 255) / 256, 256>>>();
    }
    {
        dim3 grid(NS * (NHW / 128), NHW / 128, NB);
        gemm_max_kernel<<<grid, 256>>>();
    }
    {
        int total = NB * NCLS * OW * OW;
        resize_kernel<<<(total + 255) / 256, 256>>>(out);
    }
}

// round 10
// speedup vs baseline: 3.3392x; 2.2224x over previous
#include <cuda_runtime.h>
#include <cuda_bf16.h>
#include <math.h>
#include <cstdint>

#define NB   2
#define NM   9
#define NS   8
#define ND   256
#define NH   48
#define NHW  2304
#define NCLS 4
#define OW   224
#define KB2  512      // bf16 per row: 256 hi + 256 lo

// -------- device scratch --------
__device__ __align__(16) __nv_bfloat16 g_qn_bf[(size_t)NB * NHW * KB2];
__device__ __align__(16) __nv_bfloat16 g_sn_bf[(size_t)NB * NS * NHW * KB2];
__device__ __align__(16) unsigned char g_cmask[NB * NS * NHW];
__device__ unsigned int g_logits[NB * NCLS * NHW];

// ---- order-preserving float<->uint for atomicMax ----
__device__ __forceinline__ unsigned enc_f(float f) {
    unsigned u = __float_as_uint(f);
    return (u & 0x80000000u) ? ~u : (u | 0x80000000u);
}
__device__ __forceinline__ float dec_f(unsigned e) {
    return (e & 0x80000000u) ? __uint_as_float(e & 0x7FFFFFFFu)
                             : __uint_as_float(~e);
}

__device__ __forceinline__ uint32_t smem_u32(const void* p) {
    uint32_t a;
    asm("{ .reg .u64 t; cvta.to.shared.u64 t, %1; cvt.u32.u64 %0, t; }" : "=r"(a) : "l"(p));
    return a;
}
__device__ __forceinline__ void cpa16(uint32_t saddr, const void* g) {
    asm volatile("cp.async.cg.shared.global [%0], [%1], 16;" :: "r"(saddr), "l"(g));
}
__device__ __forceinline__ void ldsm4(uint32_t* r, uint32_t addr) {
    asm volatile("ldmatrix.sync.aligned.m8n8.x4.shared.b16 {%0,%1,%2,%3}, [%4];"
        : "=r"(r[0]), "=r"(r[1]), "=r"(r[2]), "=r"(r[3]) : "r"(addr));
}
__device__ __forceinline__ void mma16816(float* c, const uint32_t* a, const uint32_t* b) {
    asm volatile(
        "mma.sync.aligned.m16n8k16.row.col.f32.bf16.bf16.f32 "
        "{%0,%1,%2,%3}, {%4,%5,%6,%7}, {%8,%9}, {%0,%1,%2,%3};"
        : "+f"(c[0]), "+f"(c[1]), "+f"(c[2]), "+f"(c[3])
        : "r"(a[0]), "r"(a[1]), "r"(a[2]), "r"(a[3]), "r"(b[0]), "r"(b[1]));
}

// smem layout (dynamic): A = 8 chunks x 16KB (128 rows x 64 bf16), B = 2 x 16KB
#define SMA_OFF   0
#define SMB_OFF   131072
#define SM_TOTAL  163840

// -------- 1) normalize + bf16 hi/lo split, pixel-major output --------
__global__ void normalize_split_kernel(const float* __restrict__ emb) {
    __shared__ float tile[256][33];
    __shared__ float red[8][32];
    __shared__ float inv_s[32];

    int bid = blockIdx.x;
    int pg = bid % (NHW / 32);
    int m  = (bid / (NHW / 32)) % NM;
    int b  = bid / ((NHW / 32) * NM);
    int pixbase = pg * 32;
    int t = threadIdx.x;

    const float* src = emb + ((size_t)(b * NM + m) * ND) * NHW + pixbase;
#pragma unroll
    for (int it = 0; it < 32; it++) {
        int d  = it * 8 + (t >> 5);
        int px = t & 31;
        tile[d][px] = src[(size_t)d * NHW + px];
    }
    __syncthreads();
    {
        int px = t & 31, part = t >> 5;
        float ps = 0.f;
#pragma unroll
        for (int dd = 0; dd < 32; dd++) {
            float v = tile[part * 32 + dd][px];
            ps += v * v;
        }
        red[part][px] = ps;
    }
    __syncthreads();
    if (t < 32) {
        float s = 0.f;
#pragma unroll
        for (int p = 0; p < 8; p++) s += red[p][t];
        inv_s[t] = 1.0f / fmaxf(sqrtf(s), 1e-12f);
    }
    __syncthreads();

    __nv_bfloat16* dst = (m == 0)
        ? (g_qn_bf + (size_t)(b * NHW + pixbase) * KB2)
        : (g_sn_bf + (size_t)((b * NS + (m - 1)) * NHW + pixbase) * KB2);

    int w = t >> 5, lane = t & 31;
#pragma unroll
    for (int pp = 0; pp < 4; pp++) {
        int p = w * 4 + pp;
        float inv = inv_s[p];
        __nv_bfloat16* row = dst + (size_t)p * KB2;
#pragma unroll
        for (int i = 0; i < 8; i++) {
            int d = i * 32 + lane;
            float v = tile[d][p] * inv;
            __nv_bfloat16 hi = __float2bfloat16(v);
            __nv_bfloat16 lo = __float2bfloat16(v - __bfloat162float(hi));
            row[d]       = hi;
            row[256 + d] = lo;
        }
    }
}

// -------- 2) class bitmask per key --------
__global__ void cmask_kernel(const float* __restrict__ pm) {
    int idx = blockIdx.x * blockDim.x + threadIdx.x;
    if (idx >= NB * NS * NHW) return;
    int pix = idx % NHW;
    int tt  = idx / NHW;
    int m   = tt % NS;
    int b   = tt / NS;
    const float* base = pm + ((size_t)(b * NS + m) * NCLS) * NHW + pix;
    unsigned msk = 0;
    if (base[1 * NHW] != 0.f) msk |= 2u;
    if (base[2 * NHW] != 0.f) msk |= 4u;
    if (base[3 * NHW] != 0.f) msk |= 8u;
    if (msk == 0u) msk = 1u;
    g_cmask[idx] = (unsigned char)msk;
}

// -------- 3) init logits --------
__global__ void init_logits_kernel() {
    int idx = blockIdx.x * blockDim.x + threadIdx.x;
    if (idx < NB * NCLS * NHW) g_logits[idx] = 0x007FFFFFu; // enc(-inf)
}

// -------- 4) HMMA (mma.sync bf16) GEMM + per-class masked max --------
// grid (m=8, qt=18, b=2); 256 threads = 8 warps, each 64x32 of the 128x128 tile.
__global__ __launch_bounds__(256, 1)
void gemm_mma_kernel() {
    extern __shared__ char smem[];
    const int m  = blockIdx.x;
    const int qt = blockIdx.y;
    const int b  = blockIdx.z;
    const int tid  = threadIdx.x;
    const int wid  = tid >> 5;
    const int lane = tid & 31;
    const int wm = wid & 1;          // 0..1 : m offset wm*64
    const int wn = wid >> 1;         // 0..3 : n offset wn*32
    const uint32_t sbase = smem_u32(smem);
    const uint32_t sA = sbase + SMA_OFF;
    const uint32_t sB = sbase + SMB_OFF;

    const __nv_bfloat16* qsrc = g_qn_bf + (size_t)(b * NHW + qt * 128) * KB2;
    const __nv_bfloat16* ssrc = g_sn_bf + (size_t)((b * NS + m) * NHW) * KB2;
    const unsigned char* cm_base = g_cmask + (b * NS + m) * NHW;

    // ---- prologue: A tile (128 rows x 512 bf16 -> 8 swizzled chunks) + B chunk 0
#pragma unroll
    for (int i = 0; i < 32; i++) {
        int id  = tid + i * 256;
        int r   = id >> 6;          // 0..127
        int gu  = id & 63;          // global 16B unit
        int ch  = gu >> 3;
        int u   = gu & 7;
        uint32_t saddr = sA + ch * 16384 + r * 128 + ((u ^ (r & 7)) << 4);
        cpa16(saddr, qsrc + (size_t)r * KB2 + gu * 8);
    }
    {
        // B chunk 0 (kt=0, c=0): cols [0,64)
#pragma unroll
        for (int i = 0; i < 4; i++) {
            int id = tid + i * 256;
            int r  = id >> 3;
            int u  = id & 7;
            uint32_t saddr = sB + r * 128 + ((u ^ (r & 7)) << 4);
            cpa16(saddr, ssrc + (size_t)r * KB2 + u * 8);
        }
    }
    asm volatile("cp.async.commit_group;");

    float acc[4][4][4];
#pragma unroll
    for (int mt = 0; mt < 4; mt++)
#pragma unroll
        for (int nt = 0; nt < 4; nt++)
#pragma unroll
            for (int e = 0; e < 4; e++) acc[mt][nt][e] = 0.f;

    float cmax[4][2][4];
#pragma unroll
    for (int mt = 0; mt < 4; mt++)
#pragma unroll
        for (int h = 0; h < 2; h++)
#pragma unroll
            for (int n = 0; n < NCLS; n++) cmax[mt][h][n] = -INFINITY;

    const int TOTAL = 18 * 8;  // 144 B chunks
#pragma unroll 1
    for (int g = 0; g < TOTAL; g++) {
        if (g + 1 < TOTAL) {
            int g2 = g + 1;
            int kt2 = g2 >> 3, c2 = g2 & 7;
            int colbase = (c2 < 4) ? c2 * 64 : 256 + (c2 - 4) * 64;
            uint32_t bufo = (g2 & 1) * 16384;
#pragma unroll
            for (int i = 0; i < 4; i++) {
                int id = tid + i * 256;
                int r  = id >> 3;
                int u  = id & 7;
                uint32_t saddr = sB + bufo + r * 128 + ((u ^ (r & 7)) << 4);
                cpa16(saddr, ssrc + (size_t)(kt2 * 128 + r) * KB2 + colbase + u * 8);
            }
            asm volatile("cp.async.commit_group;");
            asm volatile("cp.async.wait_group 1;");
        } else {
            asm volatile("cp.async.wait_group 0;");
        }
        __syncthreads();

        // ---- MMA on B chunk g ----
        const int c = g & 7;
        const uint32_t bbase = sB + (g & 1) * 16384;
        const int nac = (c < 4) ? 2 : 1;
        const int ac0 = (c < 4) ? c : (c - 4);
#pragma unroll 1
        for (int ai = 0; ai < nac; ai++) {
            const uint32_t abase = sA + ((ai == 0) ? ac0 : (ac0 + 4)) * 16384;
#pragma unroll
            for (int kk = 0; kk < 4; kk++) {
                uint32_t af[4][4];
                {
                    int au = kk * 2 + (lane >> 4);
#pragma unroll
                    for (int mt = 0; mt < 4; mt++) {
                        int r = wm * 64 + mt * 16 + (lane & 15);
                        ldsm4(af[mt], abase + r * 128 + (((au ^ (r & 7))) << 4));
                    }
                }
                uint32_t bf[4][2];
                {
                    // B fragment: [n][k] row-major in smem -> plain ldmatrix.
                    // mat = lane>>3: ntile = mat>>1, khalf = mat&1
                    int bu = kk * 2 + ((lane >> 3) & 1);
#pragma unroll
                    for (int gg = 0; gg < 2; gg++) {
                        int r = wn * 32 + gg * 16 + ((lane & 16) ? 8 : 0) + (lane & 7);
                        uint32_t tmp[4];
                        ldsm4(tmp, bbase + r * 128 + (((bu ^ (r & 7))) << 4));
                        bf[gg * 2][0]     = tmp[0];
                        bf[gg * 2][1]     = tmp[1];
                        bf[gg * 2 + 1][0] = tmp[2];
                        bf[gg * 2 + 1][1] = tmp[3];
                    }
                }
#pragma unroll
                for (int mt = 0; mt < 4; mt++)
#pragma unroll
                    for (int nt = 0; nt < 4; nt++)
                        mma16816(acc[mt][nt], af[mt], bf[nt]);
            }
        }

        // ---- per-kt epilogue: fold acc into class maxes ----
        if (c == 7) {
            int kt = g >> 3;
#pragma unroll
            for (int nt = 0; nt < 4; nt++) {
                int key = kt * 128 + wn * 32 + nt * 8 + 2 * (lane & 3);
                unsigned cm0 = cm_base[key];
                unsigned cm1 = cm_base[key + 1];
#pragma unroll
                for (int mt = 0; mt < 4; mt++) {
                    float v00 = acc[mt][nt][0];   // (r0, n0)
                    float v01 = acc[mt][nt][1];   // (r0, n1)
                    float v10 = acc[mt][nt][2];   // (r1, n0)
                    float v11 = acc[mt][nt][3];   // (r1, n1)
#pragma unroll
                    for (int n = 0; n < NCLS; n++) {
                        if ((cm0 >> n) & 1u) {
                            cmax[mt][0][n] = fmaxf(cmax[mt][0][n], v00);
                            cmax[mt][1][n] = fmaxf(cmax[mt][1][n], v10);
                        }
                        if ((cm1 >> n) & 1u) {
                            cmax[mt][0][n] = fmaxf(cmax[mt][0][n], v01);
                            cmax[mt][1][n] = fmaxf(cmax[mt][1][n], v11);
                        }
                    }
#pragma unroll
                    for (int e = 0; e < 4; e++) acc[mt][nt][e] = 0.f;
                }
            }
        }
        __syncthreads();
    }

    // ---- reduce over 4 lanes holding different keys, then atomics ----
#pragma unroll
    for (int off = 1; off <= 2; off <<= 1)
#pragma unroll
        for (int mt = 0; mt < 4; mt++)
#pragma unroll
            for (int h = 0; h < 2; h++)
#pragma unroll
                for (int n = 0; n < NCLS; n++)
                    cmax[mt][h][n] = fmaxf(cmax[mt][h][n],
                        __shfl_xor_sync(0xffffffffu, cmax[mt][h][n], off));

    if ((lane & 3) == 0) {
        int rbase = qt * 128 + wm * 64 + (lane >> 2);
#pragma unroll
        for (int mt = 0; mt < 4; mt++)
#pragma unroll
            for (int h = 0; h < 2; h++) {
                int q = rbase + mt * 16 + h * 8;
#pragma unroll
                for (int n = 0; n < NCLS; n++)
                    atomicMax(&g_logits[(b * NCLS + n) * NHW + q],
                              enc_f(cmax[mt][h][n]));
            }
    }
}

// -------- 5) bilinear resize 48 -> 224 --------
__device__ __forceinline__ void taps(int o, int& ia, int& ib, float& wa, float& wb) {
    float x  = (o + 0.5f) * ((float)NH / (float)OW) - 0.5f;
    int   i0 = (int)floorf(x);
    float f  = x - (float)i0;
    if (i0 < 0)            { ia = 0;      ib = 0;      wa = 1.f;     wb = 0.f; }
    else if (i0 >= NH - 1) { ia = NH - 1; ib = NH - 1; wa = 1.f;     wb = 0.f; }
    else                   { ia = i0;     ib = i0 + 1; wa = 1.f - f; wb = f;   }
}

__global__ void resize_kernel(float* __restrict__ out) {
    int idx = blockIdx.x * blockDim.x + threadIdx.x;
    if (idx >= NB * NCLS * OW * OW) return;
    int ox = idx % OW;
    int oy = (idx / OW) % OW;
    int n  = (idx / (OW * OW)) % NCLS;
    int b  = idx / (NCLS * OW * OW);

    int ixa, ixb, iya, iyb;
    float wxa, wxb, wya, wyb;
    taps(ox, ixa, ixb, wxa, wxb);
    taps(oy, iya, iyb, wya, wyb);

    const unsigned* lg = g_logits + (b * NCLS + n) * NHW;
    float v = 0.f;
    if (wya > 0.f) {
        float row = 0.f;
        if (wxa > 0.f) row += wxa * dec_f(lg[iya * NH + ixa]);
        if (wxb > 0.f) row += wxb * dec_f(lg[iya * NH + ixb]);
        v += wya * row;
    }
    if (wyb > 0.f) {
        float row = 0.f;
        if (wxa > 0.f) row += wxa * dec_f(lg[iyb * NH + ixa]);
        if (wxb > 0.f) row += wxb * dec_f(lg[iyb * NH + ixb]);
        v += wyb * row;
    }
    if (n == 0 && isinf(v) && v < 0.f) v = 0.f;
    out[idx] = v;
}

// -------- launch --------
extern "C" void kernel_launch(void* const* d_in, const int* in_sizes, int n_in,
                              void* d_out, int out_size) {
    const float* emb = (const float*)d_in[0];
    const float* pm  = (const float*)d_in[1];
    float* out = (float*)d_out;

    cudaFuncSetAttribute(gemm_mma_kernel,
                         cudaFuncAttributeMaxDynamicSharedMemorySize, SM_TOTAL);

    {
        int blocks = NB * NM * (NHW / 32);   // 1296
        normalize_split_kernel<<<blocks, 256>>>(emb);
    }
    {
        int total = NB * NS * NHW;
        cmask_kernel<<<(total + 255) / 256, 256>>>(pm);
    }
    {
        int total = NB * NCLS * NHW;
        init_logits_kernel<<<(total + 255) / 256, 256>>>();
    }
    {
        dim3 grid(NS, NHW / 128, NB);        // (8, 18, 2) = 288 CTAs
        gemm_mma_kernel<<<grid, 256, SM_TOTAL>>>();
    }
    {
        int total = NB * NCLS * OW * OW;
        resize_kernel<<<(total + 255) / 256, 256>>>(out);
    }
}

// round 14
// speedup vs baseline: 3.3843x; 1.0135x over previous
#include <cuda_runtime.h>
#include <cuda_bf16.h>
#include <math.h>
#include <cstdint>

#define NB   2
#define NM   9
#define NS   8
#define ND   256
#define NH   48
#define NHW  2304
#define NCLS 4
#define OW   224
#define KB2  512      // bf16 per row: 256 hi + 256 lo

// -------- device scratch --------
__device__ __align__(16) __nv_bfloat16 g_qn_bf[(size_t)NB * NHW * KB2];
__device__ __align__(16) __nv_bfloat16 g_sn_bf[(size_t)NB * NS * NHW * KB2];
__device__ __align__(16) unsigned char g_cmask[NB * NS * NHW];
__device__ unsigned int g_logits[NB * NCLS * NHW];

// ---- order-preserving float<->uint for atomicMax ----
__device__ __forceinline__ unsigned enc_f(float f) {
    unsigned u = __float_as_uint(f);
    return (u & 0x80000000u) ? ~u : (u | 0x80000000u);
}
__device__ __forceinline__ float dec_f(unsigned e) {
    return (e & 0x80000000u) ? __uint_as_float(e & 0x7FFFFFFFu)
                             : __uint_as_float(~e);
}

__device__ __forceinline__ uint32_t smem_u32(const void* p) {
    uint32_t a;
    asm("{ .reg .u64 t; cvta.to.shared.u64 t, %1; cvt.u32.u64 %0, t; }" : "=r"(a) : "l"(p));
    return a;
}
__device__ __forceinline__ void cpa16(uint32_t saddr, const void* g) {
    asm volatile("cp.async.cg.shared.global [%0], [%1], 16;" :: "r"(saddr), "l"(g));
}
__device__ __forceinline__ void ldsm4(uint32_t* r, uint32_t addr) {
    asm volatile("ldmatrix.sync.aligned.m8n8.x4.shared.b16 {%0,%1,%2,%3}, [%4];"
        : "=r"(r[0]), "=r"(r[1]), "=r"(r[2]), "=r"(r[3]) : "r"(addr));
}
__device__ __forceinline__ void mma16816(float* c, const uint32_t* a, const uint32_t* b) {
    asm volatile(
        "mma.sync.aligned.m16n8k16.row.col.f32.bf16.bf16.f32 "
        "{%0,%1,%2,%3}, {%4,%5,%6,%7}, {%8,%9}, {%0,%1,%2,%3};"
        : "+f"(c[0]), "+f"(c[1]), "+f"(c[2]), "+f"(c[3])
        : "r"(a[0]), "r"(a[1]), "r"(a[2]), "r"(a[3]), "r"(b[0]), "r"(b[1]));
}

// smem: A = 8 chunks x 16KB (128 rows x 64 bf16), B = 4 x 16KB (4-stage)
#define SMA_OFF   0
#define SMB_OFF   131072
#define SM_TOTAL  (131072 + 4 * 16384)

// load one pass worth of fragments (A: 4 ldsm4, B: 2 ldsm4)
__device__ __forceinline__ void load_frags(
    uint32_t abase, uint32_t bbase, int kk,
    int wm, int wn, int lane, uint32_t af[4][4], uint32_t bf[4][2])
{
    int au = kk * 2 + (lane >> 4);
#pragma unroll
    for (int mt = 0; mt < 4; mt++) {
        int r = wm * 64 + mt * 16 + (lane & 15);
        ldsm4(af[mt], abase + r * 128 + ((au ^ (r & 7)) << 4));
    }
    int bu = kk * 2 + ((lane >> 3) & 1);
#pragma unroll
    for (int gg = 0; gg < 2; gg++) {
        int r = wn * 32 + gg * 16 + ((lane & 16) ? 8 : 0) + (lane & 7);
        uint32_t tmp[4];
        ldsm4(tmp, bbase + r * 128 + ((bu ^ (r & 7)) << 4));
        bf[gg * 2][0]     = tmp[0];
        bf[gg * 2][1]     = tmp[1];
        bf[gg * 2 + 1][0] = tmp[2];
        bf[gg * 2 + 1][1] = tmp[3];
    }
}

// all MMA passes for one 64-col B chunk; NAC = number of A chunks (2 or 1)
template<int NAC>
__device__ __forceinline__ void chunk_mma(
    uint32_t sA, uint32_t bbase, int ac0,
    int wm, int wn, int lane, float acc[4][4][4])
{
    uint32_t af[2][4][4], bf[2][4][2];
    load_frags(sA + (uint32_t)ac0 * 16384, bbase, 0, wm, wn, lane, af[0], bf[0]);
    const int P = NAC * 4;
#pragma unroll
    for (int p = 0; p < P; p++) {
        const int pb = p & 1;
        if (p + 1 < P) {
            const int ai = (p + 1) >> 2;
            const int kk = (p + 1) & 3;
            uint32_t abase = sA + (uint32_t)(ai ? (ac0 + 4) : ac0) * 16384;
            load_frags(abase, bbase, kk, wm, wn, lane, af[pb ^ 1], bf[pb ^ 1]);
        }
#pragma unroll
        for (int mt = 0; mt < 4; mt++)
#pragma unroll
            for (int nt = 0; nt < 4; nt++)
                mma16816(acc[mt][nt], af[pb][mt], bf[pb][nt]);
    }
}

// -------- 1) normalize + bf16 hi/lo split, pixel-major output --------
__global__ void normalize_split_kernel(const float* __restrict__ emb) {
    __shared__ float tile[256][33];
    __shared__ float red[8][32];
    __shared__ float inv_s[32];

    int bid = blockIdx.x;
    int pg = bid % (NHW / 32);
    int m  = (bid / (NHW / 32)) % NM;
    int b  = bid / ((NHW / 32) * NM);
    int pixbase = pg * 32;
    int t = threadIdx.x;

    const float* src = emb + ((size_t)(b * NM + m) * ND) * NHW + pixbase;
#pragma unroll
    for (int it = 0; it < 32; it++) {
        int d  = it * 8 + (t >> 5);
        int px = t & 31;
        tile[d][px] = src[(size_t)d * NHW + px];
    }
    __syncthreads();
    {
        int px = t & 31, part = t >> 5;
        float ps = 0.f;
#pragma unroll
        for (int dd = 0; dd < 32; dd++) {
            float v = tile[part * 32 + dd][px];
            ps += v * v;
        }
        red[part][px] = ps;
    }
    __syncthreads();
    if (t < 32) {
        float s = 0.f;
#pragma unroll
        for (int p = 0; p < 8; p++) s += red[p][t];
        inv_s[t] = 1.0f / fmaxf(sqrtf(s), 1e-12f);
    }
    __syncthreads();

    __nv_bfloat16* dst = (m == 0)
        ? (g_qn_bf + (size_t)(b * NHW + pixbase) * KB2)
        : (g_sn_bf + (size_t)((b * NS + (m - 1)) * NHW + pixbase) * KB2);

    int w = t >> 5, lane = t & 31;
#pragma unroll
    for (int pp = 0; pp < 4; pp++) {
        int p = w * 4 + pp;
        float inv = inv_s[p];
        __nv_bfloat16* row = dst + (size_t)p * KB2;
#pragma unroll
        for (int i = 0; i < 8; i++) {
            int d = i * 32 + lane;
            float v = tile[d][p] * inv;
            __nv_bfloat16 hi = __float2bfloat16(v);
            __nv_bfloat16 lo = __float2bfloat16(v - __bfloat162float(hi));
            row[d]       = hi;
            row[256 + d] = lo;
        }
    }
}

// -------- 2) class bitmask per key --------
__global__ void cmask_kernel(const float* __restrict__ pm) {
    int idx = blockIdx.x * blockDim.x + threadIdx.x;
    if (idx >= NB * NS * NHW) return;
    int pix = idx % NHW;
    int tt  = idx / NHW;
    int m   = tt % NS;
    int b   = tt / NS;
    const float* base = pm + ((size_t)(b * NS + m) * NCLS) * NHW + pix;
    unsigned msk = 0;
    if (base[1 * NHW] != 0.f) msk |= 2u;
    if (base[2 * NHW] != 0.f) msk |= 4u;
    if (base[3 * NHW] != 0.f) msk |= 8u;
    if (msk == 0u) msk = 1u;
    g_cmask[idx] = (unsigned char)msk;
}

// -------- 3) init logits --------
__global__ void init_logits_kernel() {
    int idx = blockIdx.x * blockDim.x + threadIdx.x;
    if (idx < NB * NCLS * NHW) g_logits[idx] = 0x007FFFFFu; // enc(-inf)
}

// -------- 4) HMMA GEMM + per-class masked max (4-stage pipeline) --------
__global__ __launch_bounds__(256, 1)
void gemm_mma_kernel() {
    extern __shared__ char smem[];
    const int m  = blockIdx.x;
    const int qt = blockIdx.y;
    const int b  = blockIdx.z;
    const int tid  = threadIdx.x;
    const int wid  = tid >> 5;
    const int lane = tid & 31;
    const int wm = wid & 1;
    const int wn = wid >> 1;
    const uint32_t sbase = smem_u32(smem);
    const uint32_t sA = sbase + SMA_OFF;
    const uint32_t sB = sbase + SMB_OFF;

    const __nv_bfloat16* qsrc = g_qn_bf + (size_t)(b * NHW + qt * 128) * KB2;
    const __nv_bfloat16* ssrc = g_sn_bf + (size_t)((b * NS + m) * NHW) * KB2;
    const unsigned char* cm_base = g_cmask + (b * NS + m) * NHW;

    // precomputed per-thread B-load addressing
    const int bl_r = tid >> 3;            // row stride 32 over 4 iters
    const int bl_u = tid & 7;
    const uint32_t bl_soff = (uint32_t)bl_r * 128 + (uint32_t)((bl_u ^ (bl_r & 7)) << 4);

    // ---- prologue: A tile + first 3 B chunks ----
#pragma unroll
    for (int i = 0; i < 32; i++) {
        int id  = tid + i * 256;
        int r   = id >> 6;
        int gu  = id & 63;
        int ch  = gu >> 3;
        int u   = gu & 7;
        uint32_t saddr = sA + ch * 16384 + r * 128 + ((u ^ (r & 7)) << 4);
        cpa16(saddr, qsrc + (size_t)r * KB2 + gu * 8);
    }
#pragma unroll
    for (int pg = 0; pg < 3; pg++) {
        // chunk pg: kt=0, c=pg, colbase = pg*64
        uint32_t bufo = (uint32_t)pg * 16384;
#pragma unroll
        for (int i = 0; i < 4; i++) {
            int r = bl_r + i * 32;
            int u = bl_u;
            uint32_t saddr = sB + bufo + r * 128 + ((u ^ (r & 7)) << 4);
            cpa16(saddr, ssrc + (size_t)r * KB2 + pg * 64 + u * 8);
        }
        asm volatile("cp.async.commit_group;");
    }

    float acc[4][4][4];
#pragma unroll
    for (int mt = 0; mt < 4; mt++)
#pragma unroll
        for (int nt = 0; nt < 4; nt++)
#pragma unroll
            for (int e = 0; e < 4; e++) acc[mt][nt][e] = 0.f;

    float cmax[4][2][4];
#pragma unroll
    for (int mt = 0; mt < 4; mt++)
#pragma unroll
        for (int h = 0; h < 2; h++)
#pragma unroll
            for (int n = 0; n < NCLS; n++) cmax[mt][h][n] = -INFINITY;

    const int TOTAL = 18 * 8;  // 144 chunks
#pragma unroll 1
    for (int g = 0; g < TOTAL; g++) {
        // chunk g is in commit-group g+1 of 3+g total committed so far:
        // wait_group 2 -> all but newest 2 complete -> chunk g landed.
        if (g <= TOTAL - 3)      asm volatile("cp.async.wait_group 2;");
        else if (g == TOTAL - 2) asm volatile("cp.async.wait_group 1;");
        else                     asm volatile("cp.async.wait_group 0;");
        __syncthreads();

        // issue chunk g+3 (buffer (g+3)&3 was consumed at iteration g-1;
        // the barrier above protects it)
        if (g + 3 < TOTAL) {
            int gc = g + 3;
            int kt2 = gc >> 3, c2 = gc & 7;
            int colbase = (c2 < 4) ? c2 * 64 : 256 + (c2 - 4) * 64;
            uint32_t bufo = (uint32_t)(gc & 3) * 16384;
            const __nv_bfloat16* bsrc = ssrc + (size_t)(kt2 * 128) * KB2 + colbase + bl_u * 8;
#pragma unroll
            for (int i = 0; i < 4; i++) {
                uint32_t saddr = sB + bufo + bl_soff + (uint32_t)i * 32 * 128;
                // note: swizzle repeats every 8 rows, so +32 rows keeps (u^(r&7))
                cpa16(saddr, bsrc + (size_t)(bl_r + i * 32) * KB2 - (size_t)bl_r * KB2 + (size_t)bl_r * KB2);
            }
            asm volatile("cp.async.commit_group;");
        }

        // ---- MMA on chunk g ----
        const int c = g & 7;
        const uint32_t bbase = sB + (uint32_t)(g & 3) * 16384;
        if (c < 4) chunk_mma<2>(sA, bbase, c,     wm, wn, lane, acc);
        else       chunk_mma<1>(sA, bbase, c - 4, wm, wn, lane, acc);

        // ---- per-kt epilogue ----
        if (c == 7) {
            int kt = g >> 3;
#pragma unroll
            for (int nt = 0; nt < 4; nt++) {
                int key = kt * 128 + wn * 32 + nt * 8 + 2 * (lane & 3);
                unsigned cm0 = cm_base[key];
                unsigned cm1 = cm_base[key + 1];
#pragma unroll
                for (int mt = 0; mt < 4; mt++) {
                    float v00 = acc[mt][nt][0];
                    float v01 = acc[mt][nt][1];
                    float v10 = acc[mt][nt][2];
                    float v11 = acc[mt][nt][3];
#pragma unroll
                    for (int n = 0; n < NCLS; n++) {
                        if ((cm0 >> n) & 1u) {
                            cmax[mt][0][n] = fmaxf(cmax[mt][0][n], v00);
                            cmax[mt][1][n] = fmaxf(cmax[mt][1][n], v10);
                        }
                        if ((cm1 >> n) & 1u) {
                            cmax[mt][0][n] = fmaxf(cmax[mt][0][n], v01);
                            cmax[mt][1][n] = fmaxf(cmax[mt][1][n], v11);
                        }
                    }
#pragma unroll
                    for (int e = 0; e < 4; e++) acc[mt][nt][e] = 0.f;
                }
            }
        }
    }

    // ---- reduce over 4 lanes holding different keys, then atomics ----
#pragma unroll
    for (int off = 1; off <= 2; off <<= 1)
#pragma unroll
        for (int mt = 0; mt < 4; mt++)
#pragma unroll
            for (int h = 0; h < 2; h++)
#pragma unroll
                for (int n = 0; n < NCLS; n++)
                    cmax[mt][h][n] = fmaxf(cmax[mt][h][n],
                        __shfl_xor_sync(0xffffffffu, cmax[mt][h][n], off));

    if ((lane & 3) == 0) {
        int rbase = qt * 128 + wm * 64 + (lane >> 2);
#pragma unroll
        for (int mt = 0; mt < 4; mt++)
#pragma unroll
            for (int h = 0; h < 2; h++) {
                int q = rbase + mt * 16 + h * 8;
#pragma unroll
                for (int n = 0; n < NCLS; n++)
                    atomicMax(&g_logits[(b * NCLS + n) * NHW + q],
                              enc_f(cmax[mt][h][n]));
            }
    }
}

// -------- 5) bilinear resize 48 -> 224 --------
__device__ __forceinline__ void taps(int o, int& ia, int& ib, float& wa, float& wb) {
    float x  = (o + 0.5f) * ((float)NH / (float)OW) - 0.5f;
    int   i0 = (int)floorf(x);
    float f  = x - (float)i0;
    if (i0 < 0)            { ia = 0;      ib = 0;      wa = 1.f;     wb = 0.f; }
    else if (i0 >= NH - 1) { ia = NH - 1; ib = NH - 1; wa = 1.f;     wb = 0.f; }
    else                   { ia = i0;     ib = i0 + 1; wa = 1.f - f; wb = f;   }
}

__global__ void resize_kernel(float* __restrict__ out) {
    int idx = blockIdx.x * blockDim.x + threadIdx.x;
    if (idx >= NB * NCLS * OW * OW) return;
    int ox = idx % OW;
    int oy = (idx / OW) % OW;
    int n  = (idx / (OW * OW)) % NCLS;
    int b  = idx / (NCLS * OW * OW);

    int ixa, ixb, iya, iyb;
    float wxa, wxb, wya, wyb;
    taps(ox, ixa, ixb, wxa, wxb);
    taps(oy, iya, iyb, wya, wyb);

    const unsigned* lg = g_logits + (b * NCLS + n) * NHW;
    float v = 0.f;
    if (wya > 0.f) {
        float row = 0.f;
        if (wxa > 0.f) row += wxa * dec_f(lg[iya * NH + ixa]);
        if (wxb > 0.f) row += wxb * dec_f(lg[iya * NH + ixb]);
        v += wya * row;
    }
    if (wyb > 0.f) {
        float row = 0.f;
        if (wxa > 0.f) row += wxa * dec_f(lg[iyb * NH + ixa]);
        if (wxb > 0.f) row += wxb * dec_f(lg[iyb * NH + ixb]);
        v += wyb * row;
    }
    if (n == 0 && isinf(v) && v < 0.f) v = 0.f;
    out[idx] = v;
}

// -------- launch --------
extern "C" void kernel_launch(void* const* d_in, const int* in_sizes, int n_in,
                              void* d_out, int out_size) {
    const float* emb = (const float*)d_in[0];
    const float* pm  = (const float*)d_in[1];
    float* out = (float*)d_out;

    cudaFuncSetAttribute(gemm_mma_kernel,
                         cudaFuncAttributeMaxDynamicSharedMemorySize, SM_TOTAL);

    {
        int blocks = NB * NM * (NHW / 32);   // 1296
        normalize_split_kernel<<<blocks, 256>>>(emb);
    }
    {
        int total = NB * NS * NHW;
        cmask_kernel<<<(total + 255) / 256, 256>>>(pm);
    }
    {
        int total = NB * NCLS * NHW;
        init_logits_kernel<<<(total + 255) / 256, 256>>>();
    }
    {
        dim3 grid(NS, NHW / 128, NB);        // (8, 18, 2) = 288 CTAs
        gemm_mma_kernel<<<grid, 256, SM_TOTAL>>>();
    }
    {
        int total = NB * NCLS * OW * OW;
        resize_kernel<<<(total + 255) / 256, 256>>>(out);
    }
}

// round 16
// speedup vs baseline: 7.3472x; 2.1709x over previous
#include <cuda_runtime.h>
#include <cuda_fp16.h>
#include <math.h>
#include <cstdint>

#define NB   2
#define NM   9
#define NS   8
#define ND   256
#define NH   48
#define NHW  2304
#define NCLS 4
#define OW   224
#define KHF  256      // fp16 per row (single precision pass)

// -------- device scratch --------
__device__ __align__(16) __half g_qn_hf[(size_t)NB * NHW * KHF];
__device__ __align__(16) __half g_sn_hf[(size_t)NB * NS * NHW * KHF];
__device__ __align__(16) unsigned char g_cmask[NB * NS * NHW];
__device__ unsigned int g_logits[NB * NCLS * NHW];

// ---- order-preserving float<->uint for atomicMax ----
__device__ __forceinline__ unsigned enc_f(float f) {
    unsigned u = __float_as_uint(f);
    return (u & 0x80000000u) ? ~u : (u | 0x80000000u);
}
__device__ __forceinline__ float dec_f(unsigned e) {
    return (e & 0x80000000u) ? __uint_as_float(e & 0x7FFFFFFFu)
                             : __uint_as_float(~e);
}

__device__ __forceinline__ uint32_t smem_u32(const void* p) {
    uint32_t a;
    asm("{ .reg .u64 t; cvta.to.shared.u64 t, %1; cvt.u32.u64 %0, t; }" : "=r"(a) : "l"(p));
    return a;
}
__device__ __forceinline__ void cpa16(uint32_t saddr, const void* g) {
    asm volatile("cp.async.cg.shared.global [%0], [%1], 16;" :: "r"(saddr), "l"(g));
}
__device__ __forceinline__ void ldsm4(uint32_t* r, uint32_t addr) {
    asm volatile("ldmatrix.sync.aligned.m8n8.x4.shared.b16 {%0,%1,%2,%3}, [%4];"
        : "=r"(r[0]), "=r"(r[1]), "=r"(r[2]), "=r"(r[3]) : "r"(addr));
}
__device__ __forceinline__ void mma16816(float* c, const uint32_t* a, const uint32_t* b) {
    asm volatile(
        "mma.sync.aligned.m16n8k16.row.col.f32.f16.f16.f32 "
        "{%0,%1,%2,%3}, {%4,%5,%6,%7}, {%8,%9}, {%0,%1,%2,%3};"
        : "+f"(c[0]), "+f"(c[1]), "+f"(c[2]), "+f"(c[3])
        : "r"(a[0]), "r"(a[1]), "r"(a[2]), "r"(a[3]), "r"(b[0]), "r"(b[1]));
}

// smem: A = 4 chunks x 16KB (128 rows x 64 fp16), B = 4 x 16KB (4-stage)
#define SMA_OFF   0
#define SMB_OFF   65536
#define SM_TOTAL  (65536 + 4 * 16384)

// load one pass worth of fragments (A: 4 ldsm4, B: 2 ldsm4)
__device__ __forceinline__ void load_frags(
    uint32_t abase, uint32_t bbase, int kk,
    int wm, int wn, int lane, uint32_t af[4][4], uint32_t bf[4][2])
{
    int au = kk * 2 + (lane >> 4);
#pragma unroll
    for (int mt = 0; mt < 4; mt++) {
        int r = wm * 64 + mt * 16 + (lane & 15);
        ldsm4(af[mt], abase + r * 128 + ((au ^ (r & 7)) << 4));
    }
    int bu = kk * 2 + ((lane >> 3) & 1);
#pragma unroll
    for (int gg = 0; gg < 2; gg++) {
        int r = wn * 32 + gg * 16 + ((lane & 16) ? 8 : 0) + (lane & 7);
        uint32_t tmp[4];
        ldsm4(tmp, bbase + r * 128 + ((bu ^ (r & 7)) << 4));
        bf[gg * 2][0]     = tmp[0];
        bf[gg * 2][1]     = tmp[1];
        bf[gg * 2 + 1][0] = tmp[2];
        bf[gg * 2 + 1][1] = tmp[3];
    }
}

// all 4 K-passes for one 64-col chunk (A chunk == B chunk index)
__device__ __forceinline__ void chunk_mma(
    uint32_t abase, uint32_t bbase,
    int wm, int wn, int lane, float acc[4][4][4])
{
    uint32_t af[2][4][4], bf[2][4][2];
    load_frags(abase, bbase, 0, wm, wn, lane, af[0], bf[0]);
#pragma unroll
    for (int p = 0; p < 4; p++) {
        const int pb = p & 1;
        if (p + 1 < 4)
            load_frags(abase, bbase, p + 1, wm, wn, lane, af[pb ^ 1], bf[pb ^ 1]);
#pragma unroll
        for (int mt = 0; mt < 4; mt++)
#pragma unroll
            for (int nt = 0; nt < 4; nt++)
                mma16816(acc[mt][nt], af[pb][mt], bf[pb][nt]);
    }
}

// -------- 1) normalize to fp16, pixel-major output --------
__global__ void normalize_kernel(const float* __restrict__ emb) {
    __shared__ float tile[256][33];
    __shared__ float red[8][32];
    __shared__ float inv_s[32];

    int bid = blockIdx.x;
    int pg = bid % (NHW / 32);
    int m  = (bid / (NHW / 32)) % NM;
    int b  = bid / ((NHW / 32) * NM);
    int pixbase = pg * 32;
    int t = threadIdx.x;

    const float* src = emb + ((size_t)(b * NM + m) * ND) * NHW + pixbase;
#pragma unroll
    for (int it = 0; it < 32; it++) {
        int d  = it * 8 + (t >> 5);
        int px = t & 31;
        tile[d][px] = src[(size_t)d * NHW + px];
    }
    __syncthreads();
    {
        int px = t & 31, part = t >> 5;
        float ps = 0.f;
#pragma unroll
        for (int dd = 0; dd < 32; dd++) {
            float v = tile[part * 32 + dd][px];
            ps += v * v;
        }
        red[part][px] = ps;
    }
    __syncthreads();
    if (t < 32) {
        float s = 0.f;
#pragma unroll
        for (int p = 0; p < 8; p++) s += red[p][t];
        inv_s[t] = 1.0f / fmaxf(sqrtf(s), 1e-12f);
    }
    __syncthreads();

    __half* dst = (m == 0)
        ? (g_qn_hf + (size_t)(b * NHW + pixbase) * KHF)
        : (g_sn_hf + (size_t)((b * NS + (m - 1)) * NHW + pixbase) * KHF);

    int w = t >> 5, lane = t & 31;
#pragma unroll
    for (int pp = 0; pp < 4; pp++) {
        int p = w * 4 + pp;
        float inv = inv_s[p];
        __half* row = dst + (size_t)p * KHF;
#pragma unroll
        for (int i = 0; i < 8; i++) {
            int d = i * 32 + lane;
            row[d] = __float2half_rn(tile[d][p] * inv);
        }
    }
}

// -------- 2) class bitmask per key --------
__global__ void cmask_kernel(const float* __restrict__ pm) {
    int idx = blockIdx.x * blockDim.x + threadIdx.x;
    if (idx >= NB * NS * NHW) return;
    int pix = idx % NHW;
    int tt  = idx / NHW;
    int m   = tt % NS;
    int b   = tt / NS;
    const float* base = pm + ((size_t)(b * NS + m) * NCLS) * NHW + pix;
    unsigned msk = 0;
    if (base[1 * NHW] != 0.f) msk |= 2u;
    if (base[2 * NHW] != 0.f) msk |= 4u;
    if (base[3 * NHW] != 0.f) msk |= 8u;
    if (msk == 0u) msk = 1u;
    g_cmask[idx] = (unsigned char)msk;
}

// -------- 3) init logits --------
__global__ void init_logits_kernel() {
    int idx = blockIdx.x * blockDim.x + threadIdx.x;
    if (idx < NB * NCLS * NHW) g_logits[idx] = 0x007FFFFFu; // enc(-inf)
}

// -------- 4) HMMA fp16 GEMM + per-class masked max (4-stage pipeline) --------
__global__ __launch_bounds__(256, 1)
void gemm_mma_kernel() {
    extern __shared__ char smem[];
    const int m  = blockIdx.x;
    const int qt = blockIdx.y;
    const int b  = blockIdx.z;
    const int tid  = threadIdx.x;
    const int wid  = tid >> 5;
    const int lane = tid & 31;
    const int wm = wid & 1;
    const int wn = wid >> 1;
    const uint32_t sbase = smem_u32(smem);
    const uint32_t sA = sbase + SMA_OFF;
    const uint32_t sB = sbase + SMB_OFF;

    const __half* qsrc = g_qn_hf + (size_t)(b * NHW + qt * 128) * KHF;
    const __half* ssrc = g_sn_hf + (size_t)((b * NS + m) * NHW) * KHF;
    const unsigned char* cm_base = g_cmask + (b * NS + m) * NHW;

    const int bl_r = tid >> 3;   // 0..31, +32 per iter
    const int bl_u = tid & 7;

    // ---- prologue: A tile (128 rows x 256 fp16 -> 4 chunks) + B chunks 0..2 ----
#pragma unroll
    for (int i = 0; i < 16; i++) {
        int id  = tid + i * 256;
        int r   = id >> 5;          // 0..127
        int gu  = id & 31;          // 16B unit within row (32 units = 512B)
        int ch  = gu >> 3;
        int u   = gu & 7;
        uint32_t saddr = sA + ch * 16384 + r * 128 + ((u ^ (r & 7)) << 4);
        cpa16(saddr, qsrc + (size_t)r * KHF + gu * 8);
    }
#pragma unroll
    for (int pg = 0; pg < 3; pg++) {
        // chunk pg: kt=0, c=pg, col elem base = pg*64
        uint32_t bufo = (uint32_t)pg * 16384;
#pragma unroll
        for (int i = 0; i < 4; i++) {
            int r = bl_r + i * 32;
            uint32_t saddr = sB + bufo + r * 128 + ((bl_u ^ (r & 7)) << 4);
            cpa16(saddr, ssrc + (size_t)r * KHF + pg * 64 + bl_u * 8);
        }
        asm volatile("cp.async.commit_group;");
    }

    float acc[4][4][4];
#pragma unroll
    for (int mt = 0; mt < 4; mt++)
#pragma unroll
        for (int nt = 0; nt < 4; nt++)
#pragma unroll
            for (int e = 0; e < 4; e++) acc[mt][nt][e] = 0.f;

    float cmax[4][2][4];
#pragma unroll
    for (int mt = 0; mt < 4; mt++)
#pragma unroll
        for (int h = 0; h < 2; h++)
#pragma unroll
            for (int n = 0; n < NCLS; n++) cmax[mt][h][n] = -INFINITY;

    const int TOTAL = 18 * 4;  // 72 chunks (4 x 64 cols per key tile)
#pragma unroll 1
    for (int g = 0; g < TOTAL; g++) {
        // chunk g is in commit-group g+1 of g+3 committed: wait all but newest 2
        if (g <= TOTAL - 3)      asm volatile("cp.async.wait_group 2;");
        else if (g == TOTAL - 2) asm volatile("cp.async.wait_group 1;");
        else                     asm volatile("cp.async.wait_group 0;");
        __syncthreads();

        // issue chunk g+3 (buffer consumed at iteration g-1; barrier protects)
        if (g + 3 < TOTAL) {
            int gc = g + 3;
            int kt2 = gc >> 2, c2 = gc & 3;
            uint32_t bufo = (uint32_t)(gc & 3) * 16384;
            const __half* bsrc = ssrc + (size_t)(kt2 * 128) * KHF + c2 * 64 + bl_u * 8;
#pragma unroll
            for (int i = 0; i < 4; i++) {
                int r = bl_r + i * 32;
                uint32_t saddr = sB + bufo + r * 128 + ((bl_u ^ (r & 7)) << 4);
                cpa16(saddr, bsrc + (size_t)r * KHF);
            }
            asm volatile("cp.async.commit_group;");
        }

        // ---- MMA on chunk g: A chunk c pairs with B chunk c ----
        const int c = g & 3;
        chunk_mma(sA + (uint32_t)c * 16384, sB + (uint32_t)(g & 3) * 16384,
                  wm, wn, lane, acc);

        // ---- per-kt epilogue ----
        if (c == 3) {
            int kt = g >> 2;
#pragma unroll
            for (int nt = 0; nt < 4; nt++) {
                int key = kt * 128 + wn * 32 + nt * 8 + 2 * (lane & 3);
                unsigned cm0 = cm_base[key];
                unsigned cm1 = cm_base[key + 1];
#pragma unroll
                for (int mt = 0; mt < 4; mt++) {
                    float v00 = acc[mt][nt][0];
                    float v01 = acc[mt][nt][1];
                    float v10 = acc[mt][nt][2];
                    float v11 = acc[mt][nt][3];
#pragma unroll
                    for (int n = 0; n < NCLS; n++) {
                        if ((cm0 >> n) & 1u) {
                            cmax[mt][0][n] = fmaxf(cmax[mt][0][n], v00);
                            cmax[mt][1][n] = fmaxf(cmax[mt][1][n], v10);
                        }
                        if ((cm1 >> n) & 1u) {
                            cmax[mt][0][n] = fmaxf(cmax[mt][0][n], v01);
                            cmax[mt][1][n] = fmaxf(cmax[mt][1][n], v11);
                        }
                    }
#pragma unroll
                    for (int e = 0; e < 4; e++) acc[mt][nt][e] = 0.f;
                }
            }
        }
    }

    // ---- reduce over 4 lanes holding different keys, then atomics ----
#pragma unroll
    for (int off = 1; off <= 2; off <<= 1)
#pragma unroll
        for (int mt = 0; mt < 4; mt++)
#pragma unroll
            for (int h = 0; h < 2; h++)
#pragma unroll
                for (int n = 0; n < NCLS; n++)
                    cmax[mt][h][n] = fmaxf(cmax[mt][h][n],
                        __shfl_xor_sync(0xffffffffu, cmax[mt][h][n], off));

    if ((lane & 3) == 0) {
        int rbase = qt * 128 + wm * 64 + (lane >> 2);
#pragma unroll
        for (int mt = 0; mt < 4; mt++)
#pragma unroll
            for (int h = 0; h < 2; h++) {
                int q = rbase + mt * 16 + h * 8;
#pragma unroll
                for (int n = 0; n < NCLS; n++)
                    atomicMax(&g_logits[(b * NCLS + n) * NHW + q],
                              enc_f(cmax[mt][h][n]));
            }
    }
}

// -------- 5) bilinear resize 48 -> 224 --------
__device__ __forceinline__ void taps(int o, int& ia, int& ib, float& wa, float& wb) {
    float x  = (o + 0.5f) * ((float)NH / (float)OW) - 0.5f;
    int   i0 = (int)floorf(x);
    float f  = x - (float)i0;
    if (i0 < 0)            { ia = 0;      ib = 0;      wa = 1.f;     wb = 0.f; }
    else if (i0 >= NH - 1) { ia = NH - 1; ib = NH - 1; wa = 1.f;     wb = 0.f; }
    else                   { ia = i0;     ib = i0 + 1; wa = 1.f - f; wb = f;   }
}

__global__ void resize_kernel(float* __restrict__ out) {
    int idx = blockIdx.x * blockDim.x + threadIdx.x;
    if (idx >= NB * NCLS * OW * OW) return;
    int ox = idx % OW;
    int oy = (idx / OW) % OW;
    int n  = (idx / (OW * OW)) % NCLS;
    int b  = idx / (NCLS * OW * OW);

    int ixa, ixb, iya, iyb;
    float wxa, wxb, wya, wyb;
    taps(ox, ixa, ixb, wxa, wxb);
    taps(oy, iya, iyb, wya, wyb);

    const unsigned* lg = g_logits + (b * NCLS + n) * NHW;
    float v = 0.f;
    if (wya > 0.f) {
        float row = 0.f;
        if (wxa > 0.f) row += wxa * dec_f(lg[iya * NH + ixa]);
        if (wxb > 0.f) row += wxb * dec_f(lg[iya * NH + ixb]);
        v += wya * row;
    }
    if (wyb > 0.f) {
        float row = 0.f;
        if (wxa > 0.f) row += wxa * dec_f(lg[iyb * NH + ixa]);
        if (wxb > 0.f) row += wxb * dec_f(lg[iyb * NH + ixb]);
        v += wyb * row;
    }
    if (n == 0 && isinf(v) && v < 0.f) v = 0.f;
    out[idx] = v;
}

// -------- launch --------
extern "C" void kernel_launch(void* const* d_in, const int* in_sizes, int n_in,
                              void* d_out, int out_size) {
    const float* emb = (const float*)d_in[0];
    const float* pm  = (const float*)d_in[1];
    float* out = (float*)d_out;

    cudaFuncSetAttribute(gemm_mma_kernel,
                         cudaFuncAttributeMaxDynamicSharedMemorySize, SM_TOTAL);

    {
        int blocks = NB * NM * (NHW / 32);   // 1296
        normalize_kernel<<<blocks, 256>>>(emb);
    }
    {
        int total = NB * NS * NHW;
        cmask_kernel<<<(total + 255) / 256, 256>>>(pm);
    }
    {
        int total = NB * NCLS * NHW;
        init_logits_kernel<<<(total + 255) / 256, 256>>>();
    }
    {
        dim3 grid(NS, NHW / 128, NB);        // (8, 18, 2) = 288 CTAs
        gemm_mma_kernel<<<grid, 256, SM_TOTAL>>>();
    }
    {
        int total = NB * NCLS * OW * OW;
        resize_kernel<<<(total + 255) / 256, 256>>>(out);
    }
}